// round 3
// baseline (speedup 1.0000x reference)
#include <cuda_runtime.h>
#include <cstdint>
#include <math.h>

// Problem constants
#define B_   64
#define T_   4096
#define D_   128
#define H_   256
#define G_   768   // 3*H
#define C_   128

// Scratch: igates laid out [t][b][g] so each timestep is one contiguous 196KB slab.
__device__ float g_igates[(size_t)T_ * B_ * G_];
__device__ float g_hfinal[B_ * H_];

// ---------------------------------------------------------------------------
// Kernel 1: igates = x @ w_ih^T + b   (fp32 SIMT sgemm, 128x128x16 tiles)
// X: [B*T, D] row-major (b outer, t inner), W: [G, D], bias: [G]
// ---------------------------------------------------------------------------
__global__ __launch_bounds__(256) void igates_gemm(
    const float* __restrict__ X,
    const float* __restrict__ W,
    const float* __restrict__ bias)
{
    __shared__ float As[16][128];
    __shared__ float Bs[16][128];

    const int tid = threadIdx.x;
    const int mb  = blockIdx.x * 128;
    const int nb  = blockIdx.y * 128;
    const int tx  = tid & 15;    // 0..15  -> 8 output cols
    const int ty  = tid >> 4;    // 0..15  -> 8 output rows
    const int lq  = tid & 3;     // k-quad for global loads
    const int lm  = tid >> 2;    // row 0..63 for global loads

    float acc[8][8];
#pragma unroll
    for (int i = 0; i < 8; i++)
#pragma unroll
        for (int j = 0; j < 8; j++) acc[i][j] = 0.f;

    const float* Xp0 = X + (size_t)(mb + lm) * D_ + 4 * lq;
    const float* Xp1 = Xp0 + (size_t)64 * D_;
    const float* Wp0 = W + (size_t)(nb + lm) * D_ + 4 * lq;
    const float* Wp1 = Wp0 + (size_t)64 * D_;

#pragma unroll
    for (int kt = 0; kt < D_; kt += 16) {
        float4 a0 = *(const float4*)(Xp0 + kt);
        float4 a1 = *(const float4*)(Xp1 + kt);
        float4 b0 = *(const float4*)(Wp0 + kt);
        float4 b1 = *(const float4*)(Wp1 + kt);
        __syncthreads();
        As[4*lq+0][lm]    = a0.x; As[4*lq+1][lm]    = a0.y; As[4*lq+2][lm]    = a0.z; As[4*lq+3][lm]    = a0.w;
        As[4*lq+0][lm+64] = a1.x; As[4*lq+1][lm+64] = a1.y; As[4*lq+2][lm+64] = a1.z; As[4*lq+3][lm+64] = a1.w;
        Bs[4*lq+0][lm]    = b0.x; Bs[4*lq+1][lm]    = b0.y; Bs[4*lq+2][lm]    = b0.z; Bs[4*lq+3][lm]    = b0.w;
        Bs[4*lq+0][lm+64] = b1.x; Bs[4*lq+1][lm+64] = b1.y; Bs[4*lq+2][lm+64] = b1.z; Bs[4*lq+3][lm+64] = b1.w;
        __syncthreads();
#pragma unroll
        for (int k = 0; k < 16; k++) {
            float a[8], bb[8];
            *(float4*)&a[0]  = *(const float4*)&As[k][ty * 8];
            *(float4*)&a[4]  = *(const float4*)&As[k][ty * 8 + 4];
            *(float4*)&bb[0] = *(const float4*)&Bs[k][tx * 8];
            *(float4*)&bb[4] = *(const float4*)&Bs[k][tx * 8 + 4];
#pragma unroll
            for (int i = 0; i < 8; i++)
#pragma unroll
                for (int j = 0; j < 8; j++)
                    acc[i][j] = fmaf(a[i], bb[j], acc[i][j]);
        }
    }

    float bv[8];
#pragma unroll
    for (int j = 0; j < 8; j++) bv[j] = bias[nb + tx * 8 + j];

#pragma unroll
    for (int i = 0; i < 8; i++) {
        int m    = mb + ty * 8 + i;
        int bidx = m >> 12;    // m / T_
        int tt   = m & (T_ - 1);
        float* op = g_igates + ((size_t)tt * B_ + bidx) * G_ + nb + tx * 8;
        float4 v0 = make_float4(acc[i][0] + bv[0], acc[i][1] + bv[1],
                                acc[i][2] + bv[2], acc[i][3] + bv[3]);
        float4 v1 = make_float4(acc[i][4] + bv[4], acc[i][5] + bv[5],
                                acc[i][6] + bv[6], acc[i][7] + bv[7]);
        *(float4*)op       = v0;
        *(float4*)(op + 4) = v1;
    }
}

// ---------------------------------------------------------------------------
// Cluster / DSMEM helpers
// ---------------------------------------------------------------------------
__device__ __forceinline__ uint32_t smem_u32(const void* p) {
    uint32_t a;
    asm("{ .reg .u64 t; cvta.to.shared.u64 t, %1; cvt.u32.u64 %0, t; }"
        : "=r"(a) : "l"(p));
    return a;
}
__device__ __forceinline__ uint32_t mapa_u32(uint32_t a, uint32_t rank) {
    uint32_t r;
    asm("mapa.shared::cluster.u32 %0, %1, %2;" : "=r"(r) : "r"(a), "r"(rank));
    return r;
}
__device__ __forceinline__ void stc_f32(uint32_t a, float v) {
    asm volatile("st.shared::cluster.f32 [%0], %1;" :: "r"(a), "f"(v) : "memory");
}
__device__ __forceinline__ uint32_t ctarank() {
    uint32_t r;
    asm("mov.u32 %0, %%cluster_ctarank;" : "=r"(r));
    return r;
}
#define CLUSTER_SYNC() do { \
    asm volatile("barrier.cluster.arrive.aligned;" ::: "memory"); \
    asm volatile("barrier.cluster.wait.aligned;"   ::: "memory"); \
} while (0)

// ---------------------------------------------------------------------------
// Kernel 2: GRU recurrence. One cluster of 8 CTAs per 4 batches (16 clusters,
// 128 CTAs). Each CTA owns 96 rows of w_hh fully in registers (32 fp32/thread,
// 768 threads). h[256][4 batches] replicated in every CTA's SMEM; per step:
//   matvec (reg weights x SMEM h, uniform-broadcast LDS) ->
//   k-chunk reduce -> DSMEM scatter of hg to h-index owners -> cluster sync ->
//   gating (sigmoid/tanh) -> DSMEM broadcast of h_new to all 8 CTAs -> sync.
// ---------------------------------------------------------------------------
__global__ __launch_bounds__(768, 1) void gru_scan(
    const float* __restrict__ Whh,   // [G_, H_]
    const float* __restrict__ bn_g)  // [H_]
{
    __shared__ float4 h4[H_];          // h[k] -> 4 batches packed
    __shared__ float4 part[8 * 96];    // k-chunk partials [kc][r]
    __shared__ float  in_hg[3 * 32 * 4]; // incoming hg: [gate][local j][bm]

    const int tid  = threadIdx.x;
    const uint32_t crank = ctarank();
    const int bbase = (blockIdx.x >> 3) * 4;   // 4 batches per cluster

    const int warp = tid >> 5, lane = tid & 31;
    const int kc = warp / 3;                 // k-chunk 0..7 (32 k each)
    const int r  = (warp % 3) * 32 + lane;   // local gate row 0..95

    // Load this thread's 32 weights into registers (constant for all 4096 steps)
    float w[32];
    {
        const float* wrow = Whh + ((size_t)(crank * 96 + r)) * H_ + kc * 32;
#pragma unroll
        for (int i = 0; i < 32; i += 4) {
            float4 t = *(const float4*)(wrow + i);
            w[i] = t.x; w[i+1] = t.y; w[i+2] = t.z; w[i+3] = t.w;
        }
    }

    const uint32_t h_base  = smem_u32(h4);
    const uint32_t hg_base = smem_u32(in_hg);

    // Scatter setup: thread (r2,bm2) sends hg[r2][bm2] to the CTA owning h-index
    uint32_t scat_addr = 0;
    {
        const int r2 = tid >> 2, bm2 = tid & 3;
        if (tid < 384) {
            int g    = crank * 96 + r2;     // global gate row
            int gt   = g >> 8;              // gate type 0/1/2
            int j    = g & 255;             // h index
            int dest = j >> 5;              // owning CTA
            int jl   = j & 31;
            scat_addr = mapa_u32(hg_base + (((gt * 32 + jl) * 4 + bm2) * 4), dest);
        }
    }

    // Gating setup: thread (gbm,gj) owns h index jg = crank*32+gj for batch gbm
    const int gbm = tid >> 5, gj = tid & 31;
    const int jg  = crank * 32 + gj;
    float bnv = 0.f;
    uint32_t bc[8];
    if (tid < 128) {
        bnv = bn_g[jg];
#pragma unroll
        for (int d = 0; d < 8; d++)
            bc[d] = mapa_u32(h_base + ((jg * 4 + gbm) * 4), (uint32_t)d);
    }

    // h = 0
    for (int idx = tid; idx < H_; idx += 768)
        h4[idx] = make_float4(0.f, 0.f, 0.f, 0.f);
    __syncthreads();
    CLUSTER_SYNC();

    for (int t = 0; t < T_; t++) {
        // Prefetch igates for this step (consumed after sync_a, ~1.6k cyc later)
        float ig_r = 0.f, ig_z = 0.f, ig_n = 0.f;
        if (tid < 128) {
            size_t base = ((size_t)t * B_ + (bbase + gbm)) * G_ + jg;
            ig_r = g_igates[base];
            ig_z = g_igates[base + 256];
            ig_n = g_igates[base + 512];
        }

        // Matvec: 32 k-steps, uniform-address LDS.128 broadcast of h
        float a0 = 0.f, a1 = 0.f, a2 = 0.f, a3 = 0.f;
#pragma unroll
        for (int kk = 0; kk < 32; kk++) {
            float4 hv = h4[kc * 32 + kk];
            a0 = fmaf(w[kk], hv.x, a0);
            a1 = fmaf(w[kk], hv.y, a1);
            a2 = fmaf(w[kk], hv.z, a2);
            a3 = fmaf(w[kk], hv.w, a3);
        }
        part[kc * 96 + r] = make_float4(a0, a1, a2, a3);
        __syncthreads();

        // Reduce 8 k-chunks, scatter result to owning CTA via DSMEM
        if (tid < 384) {
            const float* pf = (const float*)part;
            float s = 0.f;
#pragma unroll
            for (int q = 0; q < 8; q++) s += pf[q * 384 + tid];
            stc_f32(scat_addr, s);
        }
        CLUSTER_SYNC();   // sync_a: all hg delivered, all h reads done

        // Gating + broadcast h_new to all 8 CTAs
        if (tid < 128) {
            float hr = in_hg[(gj) * 4 + gbm];
            float hz = in_hg[(32 + gj) * 4 + gbm];
            float hn = in_hg[(64 + gj) * 4 + gbm];
            float rr = 1.f / (1.f + expf(-(ig_r + hr)));
            float zz = 1.f / (1.f + expf(-(ig_z + hz)));
            float nn = tanhf(ig_n + rr * (hn + bnv));
            float hold = ((const float*)h4)[jg * 4 + gbm];
            float hnew = nn + zz * (hold - nn);
#pragma unroll
            for (int d = 0; d < 8; d++) stc_f32(bc[d], hnew);
        }
        CLUSTER_SYNC();   // sync_b: h_new visible everywhere
    }

    // Rank 0 of each cluster writes the final h for its 4 batches
    if (crank == 0) {
        for (int idx = tid; idx < 4 * H_; idx += 768) {
            int bm = idx >> 8, k = idx & 255;
            g_hfinal[(bbase + bm) * H_ + k] = ((const float*)h4)[k * 4 + bm];
        }
    }
}

// ---------------------------------------------------------------------------
// Kernel 3: out = h_final @ w_proj^T + b_proj   ([64,256] x [256,128])
// ---------------------------------------------------------------------------
__global__ __launch_bounds__(128) void proj_kernel(
    const float* __restrict__ Wp,   // [C_, H_]
    const float* __restrict__ bp,   // [C_]
    float* __restrict__ out)        // [B_, C_]
{
    __shared__ float hs[H_];
    int b = blockIdx.x;
    for (int k = threadIdx.x; k < H_; k += 128) hs[k] = g_hfinal[b * H_ + k];
    __syncthreads();
    int c = threadIdx.x;
    float acc = bp[c];
    const float* wr = Wp + (size_t)c * H_;
#pragma unroll 8
    for (int k = 0; k < H_; k++) acc = fmaf(hs[k], wr[k], acc);
    out[b * C_ + c] = acc;
}

// ---------------------------------------------------------------------------
// Launch
// ---------------------------------------------------------------------------
extern "C" void kernel_launch(void* const* d_in, const int* in_sizes, int n_in,
                              void* d_out, int out_size)
{
    const float* x      = (const float*)d_in[0];  // [B,T,D]
    const float* w_ih   = (const float*)d_in[1];  // [3H,D]
    const float* w_hh   = (const float*)d_in[2];  // [3H,H]
    const float* b      = (const float*)d_in[3];  // [3H]
    const float* bn     = (const float*)d_in[4];  // [H]
    const float* w_proj = (const float*)d_in[5];  // [C,H]
    const float* b_proj = (const float*)d_in[6];  // [C]
    float* out = (float*)d_out;

    // 1) input-side gates for all timesteps
    dim3 g1((B_ * T_) / 128, G_ / 128);
    igates_gemm<<<g1, 256>>>(x, w_ih, b);

    // 2) recurrence: 16 clusters x 8 CTAs x 768 threads
    {
        cudaLaunchConfig_t cfg = {};
        cfg.gridDim  = dim3(128, 1, 1);
        cfg.blockDim = dim3(768, 1, 1);
        cfg.dynamicSmemBytes = 0;
        cfg.stream = 0;
        cudaLaunchAttribute attr[1];
        attr[0].id = cudaLaunchAttributeClusterDimension;
        attr[0].val.clusterDim.x = 8;
        attr[0].val.clusterDim.y = 1;
        attr[0].val.clusterDim.z = 1;
        cfg.attrs = attr;
        cfg.numAttrs = 1;
        cudaLaunchKernelEx(&cfg, gru_scan, w_hh, bn);
    }

    // 3) output projection
    proj_kernel<<<B_, 128>>>(w_proj, b_proj, out);
}

// round 4
// speedup vs baseline: 1.5696x; 1.5696x over previous
#include <cuda_runtime.h>
#include <cstdint>
#include <math.h>

// Problem constants
#define B_   64
#define T_   4096
#define D_   128
#define H_   256
#define G_   768   // 3*H
#define C_   128

// Scratch: igates laid out [t][b][g] so each timestep is one contiguous slab.
__device__ float g_igates[(size_t)T_ * B_ * G_];
__device__ float g_hfinal[B_ * H_];

// ---------------------------------------------------------------------------
// Kernel 1: igates = x @ w_ih^T + b   (fp32 SIMT sgemm, 128x128x16 tiles)
// ---------------------------------------------------------------------------
__global__ __launch_bounds__(256) void igates_gemm(
    const float* __restrict__ X,
    const float* __restrict__ W,
    const float* __restrict__ bias)
{
    __shared__ float As[16][128];
    __shared__ float Bs[16][128];

    const int tid = threadIdx.x;
    const int mb  = blockIdx.x * 128;
    const int nb  = blockIdx.y * 128;
    const int tx  = tid & 15;
    const int ty  = tid >> 4;
    const int lq  = tid & 3;
    const int lm  = tid >> 2;

    float acc[8][8];
#pragma unroll
    for (int i = 0; i < 8; i++)
#pragma unroll
        for (int j = 0; j < 8; j++) acc[i][j] = 0.f;

    const float* Xp0 = X + (size_t)(mb + lm) * D_ + 4 * lq;
    const float* Xp1 = Xp0 + (size_t)64 * D_;
    const float* Wp0 = W + (size_t)(nb + lm) * D_ + 4 * lq;
    const float* Wp1 = Wp0 + (size_t)64 * D_;

#pragma unroll
    for (int kt = 0; kt < D_; kt += 16) {
        float4 a0 = *(const float4*)(Xp0 + kt);
        float4 a1 = *(const float4*)(Xp1 + kt);
        float4 b0 = *(const float4*)(Wp0 + kt);
        float4 b1 = *(const float4*)(Wp1 + kt);
        __syncthreads();
        As[4*lq+0][lm]    = a0.x; As[4*lq+1][lm]    = a0.y; As[4*lq+2][lm]    = a0.z; As[4*lq+3][lm]    = a0.w;
        As[4*lq+0][lm+64] = a1.x; As[4*lq+1][lm+64] = a1.y; As[4*lq+2][lm+64] = a1.z; As[4*lq+3][lm+64] = a1.w;
        Bs[4*lq+0][lm]    = b0.x; Bs[4*lq+1][lm]    = b0.y; Bs[4*lq+2][lm]    = b0.z; Bs[4*lq+3][lm]    = b0.w;
        Bs[4*lq+0][lm+64] = b1.x; Bs[4*lq+1][lm+64] = b1.y; Bs[4*lq+2][lm+64] = b1.z; Bs[4*lq+3][lm+64] = b1.w;
        __syncthreads();
#pragma unroll
        for (int k = 0; k < 16; k++) {
            float a[8], bb[8];
            *(float4*)&a[0]  = *(const float4*)&As[k][ty * 8];
            *(float4*)&a[4]  = *(const float4*)&As[k][ty * 8 + 4];
            *(float4*)&bb[0] = *(const float4*)&Bs[k][tx * 8];
            *(float4*)&bb[4] = *(const float4*)&Bs[k][tx * 8 + 4];
#pragma unroll
            for (int i = 0; i < 8; i++)
#pragma unroll
                for (int j = 0; j < 8; j++)
                    acc[i][j] = fmaf(a[i], bb[j], acc[i][j]);
        }
    }

    float bv[8];
#pragma unroll
    for (int j = 0; j < 8; j++) bv[j] = bias[nb + tx * 8 + j];

#pragma unroll
    for (int i = 0; i < 8; i++) {
        int m    = mb + ty * 8 + i;
        int bidx = m >> 12;
        int tt   = m & (T_ - 1);
        float* op = g_igates + ((size_t)tt * B_ + bidx) * G_ + nb + tx * 8;
        float4 v0 = make_float4(acc[i][0] + bv[0], acc[i][1] + bv[1],
                                acc[i][2] + bv[2], acc[i][3] + bv[3]);
        float4 v1 = make_float4(acc[i][4] + bv[4], acc[i][5] + bv[5],
                                acc[i][6] + bv[6], acc[i][7] + bv[7]);
        *(float4*)op       = v0;
        *(float4*)(op + 4) = v1;
    }
}

// ---------------------------------------------------------------------------
// Cluster / DSMEM / mbarrier helpers
// ---------------------------------------------------------------------------
__device__ __forceinline__ uint32_t smem_u32(const void* p) {
    uint32_t a;
    asm("{ .reg .u64 t; cvta.to.shared.u64 t, %1; cvt.u32.u64 %0, t; }"
        : "=r"(a) : "l"(p));
    return a;
}
__device__ __forceinline__ uint32_t mapa_u32(uint32_t a, uint32_t rank) {
    uint32_t r;
    asm("mapa.shared::cluster.u32 %0, %1, %2;" : "=r"(r) : "r"(a), "r"(rank));
    return r;
}
__device__ __forceinline__ uint32_t ctarank() {
    uint32_t r;
    asm("mov.u32 %0, %%cluster_ctarank;" : "=r"(r));
    return r;
}
#define CLUSTER_SYNC() do { \
    asm volatile("barrier.cluster.arrive.aligned;" ::: "memory"); \
    asm volatile("barrier.cluster.wait.aligned;"   ::: "memory"); \
} while (0)

#define MBAR_INIT(a, c) \
    asm volatile("mbarrier.init.shared.b64 [%0], %1;" :: "r"(a), "r"(c) : "memory")
#define MBAR_EXPECT_TX(a, tx) \
    asm volatile("mbarrier.arrive.expect_tx.shared.b64 _, [%0], %1;" :: "r"(a), "r"(tx) : "memory")

// Remote store with mbarrier tx completion (dest addr + dest-CTA mbarrier).
#define ST_ASYNC_F32(addr, val, mbar) \
    asm volatile("st.async.shared::cluster.mbarrier::complete_tx::bytes.b32 [%0], %1, [%2];" \
                 :: "r"(addr), "f"(val), "r"(mbar) : "memory")

__device__ __forceinline__ void mbar_wait(uint32_t addr, uint32_t phase) {
    uint32_t done;
    asm volatile(
        "{\n\t.reg .pred p;\n\t"
        "mbarrier.try_wait.parity.acquire.cluster.shared::cta.b64 p, [%1], %2;\n\t"
        "selp.b32 %0, 1, 0, p;\n\t}"
        : "=r"(done) : "r"(addr), "r"(phase) : "memory");
    while (!done) {
        asm volatile(
            "{\n\t.reg .pred p;\n\t"
            "mbarrier.try_wait.parity.acquire.cluster.shared::cta.b64 p, [%1], %2, 0x989680;\n\t"
            "selp.b32 %0, 1, 0, p;\n\t}"
            : "=r"(done) : "r"(addr), "r"(phase) : "memory");
    }
}

// Packed fp32x2 FMA (Blackwell)
#define FFMA2(acc, a, b) \
    asm("fma.rn.f32x2 %0, %1, %2, %0;" : "+l"(acc) : "l"(a), "l"(b))

__device__ __forceinline__ float2 unpack2(unsigned long long v) {
    float2 f;
    asm("mov.b64 {%0, %1}, %2;" : "=f"(f.x), "=f"(f.y) : "l"(v));
    return f;
}

// MUFU-based activations (ex2/rcp approx: rel err ~2^-22)
__device__ __forceinline__ float fast_sigmoid(float x) {
    float e, r;
    asm("ex2.approx.f32 %0, %1;" : "=f"(e) : "f"(x * -1.442695040888963f));
    asm("rcp.approx.f32 %0, %1;" : "=f"(r) : "f"(1.f + e));
    return r;
}
__device__ __forceinline__ float fast_tanh(float x) {
    float e, r;
    asm("ex2.approx.f32 %0, %1;" : "=f"(e) : "f"(x * -2.885390081777927f));
    asm("rcp.approx.f32 %0, %1;" : "=f"(r) : "f"(1.f + e));
    return fmaf(2.f, r, -1.f);
}

// ---------------------------------------------------------------------------
// Kernel 2: GRU recurrence. 16 clusters x 8 CTAs; each CTA holds 96 w_hh rows
// in registers as k-pairs (fma.rn.f32x2). Sync is fully mbarrier/st.async:
//   hg scatter  -> 1 barrier/CTA, expect_tx 1536 B/step (skew 0, proven)
//   h broadcast -> 2 barriers/CTA (ping-pong; sender skew bounded to 1 phase),
//                  expect_tx 4096 B/step, h double-buffered.
// h layout interleaved: float4 hP[buf][k2*2 + bm/2] holds
//   floats { (bm&1)*2 + (k&1) }  ->  one LDS.128 = two batches' k-pairs.
// ---------------------------------------------------------------------------
__global__ __launch_bounds__(768, 1) void gru_scan(
    const float* __restrict__ Whh,   // [G_, H_]
    const float* __restrict__ bn_g)  // [H_]
{
    __shared__ float4 hP[2][256];      // two h buffers, interleaved layout (4KB each)
    __shared__ float4 part[8 * 96];    // k-chunk partials [kc][r]
    __shared__ float  in_hg[384];      // incoming hg: [gate][local j][bm]
    __shared__ __align__(8) unsigned long long hg_mbar;
    __shared__ __align__(8) unsigned long long h_mbar[2];

    const int tid   = threadIdx.x;
    const uint32_t crank = ctarank();
    const int bbase = (blockIdx.x >> 3) * 4;

    const int warp = tid >> 5, lane = tid & 31;
    const int kc = warp / 3;                 // k-chunk 0..7 (32 k each)
    const int r  = (warp % 3) * 32 + lane;   // local gate row 0..95

    // Weights as 16 k-pair f32x2 registers (no duplication)
    unsigned long long w2[16];
    {
        const ulonglong2* wr = reinterpret_cast<const ulonglong2*>(
            Whh + (size_t)(crank * 96 + r) * H_ + kc * 32);
#pragma unroll
        for (int i = 0; i < 8; i++) { ulonglong2 v = wr[i]; w2[2*i] = v.x; w2[2*i+1] = v.y; }
    }

    const uint32_t hP_base  = smem_u32(hP);
    const uint32_t hg_base  = smem_u32(in_hg);
    const uint32_t hgm_base = smem_u32(&hg_mbar);
    const uint32_t hm_base  = smem_u32(h_mbar);

    // Scatter setup: thread (r2,bm2) sends hg[r2][bm2] to the CTA owning h-index
    uint32_t scat_addr = 0, scat_mbar = 0;
    if (tid < 384) {
        const int r2 = tid >> 2, bm2 = tid & 3;
        int g    = crank * 96 + r2;
        int gt   = g >> 8;
        int j    = g & 255;
        int dest = j >> 5;
        int jl   = j & 31;
        scat_addr = mapa_u32(hg_base + ((gt * 32 + jl) * 4 + bm2) * 4, (uint32_t)dest);
        scat_mbar = mapa_u32(hgm_base, (uint32_t)dest);
    }

    // Gating setup: thread (gbm,gj) owns h index jg = crank*32+gj for batch gbm
    const int gbm = tid >> 5, gj = tid & 31;
    const int jg  = crank * 32 + gj;
    const int hflt = (jg >> 1) * 8 + (gbm >> 1) * 4 + (gbm & 1) * 2 + (jg & 1); // float idx in buf
    float bnv = 0.f;
    if (tid < 128) bnv = bn_g[jg];

    if (tid == 0) {
        MBAR_INIT(hgm_base, 1);
        MBAR_INIT(hm_base, 1);
        MBAR_INIT(hm_base + 8, 1);
    }
    for (int i = tid; i < 512; i += 768)
        ((float4*)hP)[i] = make_float4(0.f, 0.f, 0.f, 0.f);
    __syncthreads();
    CLUSTER_SYNC();   // mbarriers + zeroed h visible cluster-wide

    for (int t = 0; t < T_; t++) {
        const int buf = t & 1;
        if (tid == 0) {
            MBAR_EXPECT_TX(hgm_base, 1536);           // 384 floats incoming
            MBAR_EXPECT_TX(hm_base + 8 * buf, 4096);  // 1024 floats incoming
        }

        // Prefetch igates (consumed after hg wait, well covered)
        float ig_r = 0.f, ig_z = 0.f, ig_n = 0.f;
        if (tid < 128) {
            size_t base = ((size_t)t * B_ + (bbase + gbm)) * G_ + jg;
            ig_r = g_igates[base];
            ig_z = g_igates[base + 256];
            ig_n = g_igates[base + 512];
        }

        // Matvec: 16 k-pairs, packed f32x2 FMAs; 2 LDS.128 feed 4 batches/pair
        unsigned long long a0 = 0ull, a1 = 0ull, a2 = 0ull, a3 = 0ull;
        {
            const ulonglong2* hv = reinterpret_cast<const ulonglong2*>(&hP[buf][kc * 32]);
#pragma unroll
            for (int kp = 0; kp < 16; kp++) {
                ulonglong2 U0 = hv[2 * kp];      // bm0,bm1 k-pairs
                ulonglong2 U1 = hv[2 * kp + 1];  // bm2,bm3 k-pairs
                FFMA2(a0, w2[kp], U0.x);
                FFMA2(a1, w2[kp], U0.y);
                FFMA2(a2, w2[kp], U1.x);
                FFMA2(a3, w2[kp], U1.y);
            }
        }
        {
            float2 f0 = unpack2(a0), f1 = unpack2(a1), f2 = unpack2(a2), f3 = unpack2(a3);
            part[kc * 96 + r] = make_float4(f0.x + f0.y, f1.x + f1.y, f2.x + f2.y, f3.x + f3.y);
        }
        __syncthreads();

        // Reduce 8 k-chunks; deliver hg to owner CTA via st.async (+tx)
        if (tid < 384) {
            const float* pf = (const float*)part;
            float s = 0.f;
#pragma unroll
            for (int q = 0; q < 8; q++) s += pf[q * 384 + tid];
            ST_ASYNC_F32(scat_addr, s, scat_mbar);
        }

        // Gating threads: wait hg, compute, broadcast h_new to all 8 CTAs
        if (tid < 128) {
            mbar_wait(hgm_base, (uint32_t)(t & 1));
            float hr = in_hg[gj * 4 + gbm];
            float hz = in_hg[128 + gj * 4 + gbm];
            float hn = in_hg[256 + gj * 4 + gbm];
            float rr = fast_sigmoid(ig_r + hr);
            float zz = fast_sigmoid(ig_z + hz);
            float nn = fast_tanh(ig_n + rr * (hn + bnv));
            float hold = ((const float*)hP)[buf * 1024 + hflt];
            float hnew = nn + zz * (hold - nn);
            uint32_t dst  = hP_base + (buf ^ 1) * 4096 + hflt * 4;
            uint32_t mdst = hm_base + 8 * buf;
#pragma unroll
            for (int d = 0; d < 8; d++)
                ST_ASYNC_F32(mapa_u32(dst, (uint32_t)d), hnew, mapa_u32(mdst, (uint32_t)d));
        }

        // Everyone: wait for the full next-h to land (4096 B from 8 CTAs)
        mbar_wait(hm_base + 8 * buf, (uint32_t)((t >> 1) & 1));
    }

    // Final h lives in buffer 0 (T even). Rank 0 writes its cluster's 4 batches.
    if (crank == 0) {
        const float* hf = (const float*)hP;  // buffer 0
        for (int idx = tid; idx < 4 * H_; idx += 768) {
            int bm = idx >> 8, k = idx & 255;
            int fo = (k >> 1) * 8 + (bm >> 1) * 4 + (bm & 1) * 2 + (k & 1);
            g_hfinal[(bbase + bm) * H_ + k] = hf[fo];
        }
    }
    CLUSTER_SYNC();
}

// ---------------------------------------------------------------------------
// Kernel 3: out = h_final @ w_proj^T + b_proj
// ---------------------------------------------------------------------------
__global__ __launch_bounds__(128) void proj_kernel(
    const float* __restrict__ Wp,
    const float* __restrict__ bp,
    float* __restrict__ out)
{
    __shared__ float hs[H_];
    int b = blockIdx.x;
    for (int k = threadIdx.x; k < H_; k += 128) hs[k] = g_hfinal[b * H_ + k];
    __syncthreads();
    int c = threadIdx.x;
    float acc = bp[c];
    const float* wr = Wp + (size_t)c * H_;
#pragma unroll 8
    for (int k = 0; k < H_; k++) acc = fmaf(hs[k], wr[k], acc);
    out[b * C_ + c] = acc;
}

// ---------------------------------------------------------------------------
// Launch
// ---------------------------------------------------------------------------
extern "C" void kernel_launch(void* const* d_in, const int* in_sizes, int n_in,
                              void* d_out, int out_size)
{
    const float* x      = (const float*)d_in[0];
    const float* w_ih   = (const float*)d_in[1];
    const float* w_hh   = (const float*)d_in[2];
    const float* b      = (const float*)d_in[3];
    const float* bn     = (const float*)d_in[4];
    const float* w_proj = (const float*)d_in[5];
    const float* b_proj = (const float*)d_in[6];
    float* out = (float*)d_out;

    dim3 g1((B_ * T_) / 128, G_ / 128);
    igates_gemm<<<g1, 256>>>(x, w_ih, b);

    {
        cudaLaunchConfig_t cfg = {};
        cfg.gridDim  = dim3(128, 1, 1);
        cfg.blockDim = dim3(768, 1, 1);
        cfg.dynamicSmemBytes = 0;
        cfg.stream = 0;
        cudaLaunchAttribute attr[1];
        attr[0].id = cudaLaunchAttributeClusterDimension;
        attr[0].val.clusterDim.x = 8;
        attr[0].val.clusterDim.y = 1;
        attr[0].val.clusterDim.z = 1;
        cfg.attrs = attr;
        cfg.numAttrs = 1;
        cudaLaunchKernelEx(&cfg, gru_scan, w_hh, bn);
    }

    proj_kernel<<<B_, 128>>>(w_proj, b_proj, out);
}

// round 5
// speedup vs baseline: 1.6767x; 1.0682x over previous
#include <cuda_runtime.h>
#include <cstdint>
#include <math.h>

// Problem constants
#define B_   64
#define T_   4096
#define D_   128
#define H_   256
#define G_   768   // 3*H
#define C_   128

// Scratch: igates laid out [t][b][g] so each timestep is one contiguous slab.
__device__ float g_igates[(size_t)T_ * B_ * G_];
__device__ float g_hfinal[B_ * H_];

// ---------------------------------------------------------------------------
// Kernel 1: igates = x @ w_ih^T + b   (fp32 SIMT sgemm, 128x128x16 tiles)
// ---------------------------------------------------------------------------
__global__ __launch_bounds__(256) void igates_gemm(
    const float* __restrict__ X,
    const float* __restrict__ W,
    const float* __restrict__ bias)
{
    __shared__ float As[16][128];
    __shared__ float Bs[16][128];

    const int tid = threadIdx.x;
    const int mb  = blockIdx.x * 128;
    const int nb  = blockIdx.y * 128;
    const int tx  = tid & 15;
    const int ty  = tid >> 4;
    const int lq  = tid & 3;
    const int lm  = tid >> 2;

    float acc[8][8];
#pragma unroll
    for (int i = 0; i < 8; i++)
#pragma unroll
        for (int j = 0; j < 8; j++) acc[i][j] = 0.f;

    const float* Xp0 = X + (size_t)(mb + lm) * D_ + 4 * lq;
    const float* Xp1 = Xp0 + (size_t)64 * D_;
    const float* Wp0 = W + (size_t)(nb + lm) * D_ + 4 * lq;
    const float* Wp1 = Wp0 + (size_t)64 * D_;

#pragma unroll
    for (int kt = 0; kt < D_; kt += 16) {
        float4 a0 = *(const float4*)(Xp0 + kt);
        float4 a1 = *(const float4*)(Xp1 + kt);
        float4 b0 = *(const float4*)(Wp0 + kt);
        float4 b1 = *(const float4*)(Wp1 + kt);
        __syncthreads();
        As[4*lq+0][lm]    = a0.x; As[4*lq+1][lm]    = a0.y; As[4*lq+2][lm]    = a0.z; As[4*lq+3][lm]    = a0.w;
        As[4*lq+0][lm+64] = a1.x; As[4*lq+1][lm+64] = a1.y; As[4*lq+2][lm+64] = a1.z; As[4*lq+3][lm+64] = a1.w;
        Bs[4*lq+0][lm]    = b0.x; Bs[4*lq+1][lm]    = b0.y; Bs[4*lq+2][lm]    = b0.z; Bs[4*lq+3][lm]    = b0.w;
        Bs[4*lq+0][lm+64] = b1.x; Bs[4*lq+1][lm+64] = b1.y; Bs[4*lq+2][lm+64] = b1.z; Bs[4*lq+3][lm+64] = b1.w;
        __syncthreads();
#pragma unroll
        for (int k = 0; k < 16; k++) {
            float a[8], bb[8];
            *(float4*)&a[0]  = *(const float4*)&As[k][ty * 8];
            *(float4*)&a[4]  = *(const float4*)&As[k][ty * 8 + 4];
            *(float4*)&bb[0] = *(const float4*)&Bs[k][tx * 8];
            *(float4*)&bb[4] = *(const float4*)&Bs[k][tx * 8 + 4];
#pragma unroll
            for (int i = 0; i < 8; i++)
#pragma unroll
                for (int j = 0; j < 8; j++)
                    acc[i][j] = fmaf(a[i], bb[j], acc[i][j]);
        }
    }

    float bv[8];
#pragma unroll
    for (int j = 0; j < 8; j++) bv[j] = bias[nb + tx * 8 + j];

#pragma unroll
    for (int i = 0; i < 8; i++) {
        int m    = mb + ty * 8 + i;
        int bidx = m >> 12;
        int tt   = m & (T_ - 1);
        float* op = g_igates + ((size_t)tt * B_ + bidx) * G_ + nb + tx * 8;
        float4 v0 = make_float4(acc[i][0] + bv[0], acc[i][1] + bv[1],
                                acc[i][2] + bv[2], acc[i][3] + bv[3]);
        float4 v1 = make_float4(acc[i][4] + bv[4], acc[i][5] + bv[5],
                                acc[i][6] + bv[6], acc[i][7] + bv[7]);
        *(float4*)op       = v0;
        *(float4*)(op + 4) = v1;
    }
}

// ---------------------------------------------------------------------------
// Cluster / DSMEM / mbarrier helpers
// ---------------------------------------------------------------------------
__device__ __forceinline__ uint32_t smem_u32(const void* p) {
    uint32_t a;
    asm("{ .reg .u64 t; cvta.to.shared.u64 t, %1; cvt.u32.u64 %0, t; }"
        : "=r"(a) : "l"(p));
    return a;
}
__device__ __forceinline__ uint32_t mapa_u32(uint32_t a, uint32_t rank) {
    uint32_t r;
    asm("mapa.shared::cluster.u32 %0, %1, %2;" : "=r"(r) : "r"(a), "r"(rank));
    return r;
}
__device__ __forceinline__ uint32_t ctarank() {
    uint32_t r;
    asm("mov.u32 %0, %%cluster_ctarank;" : "=r"(r));
    return r;
}
#define CLUSTER_SYNC() do { \
    asm volatile("barrier.cluster.arrive.aligned;" ::: "memory"); \
    asm volatile("barrier.cluster.wait.aligned;"   ::: "memory"); \
} while (0)

#define MBAR_INIT(a, c) \
    asm volatile("mbarrier.init.shared.b64 [%0], %1;" :: "r"(a), "r"(c) : "memory")
#define MBAR_EXPECT_TX(a, tx) \
    asm volatile("mbarrier.arrive.expect_tx.shared.b64 _, [%0], %1;" :: "r"(a), "r"(tx) : "memory")

// Remote 16B store with mbarrier tx completion.
#define ST_ASYNC_V4(addr, v, mbar) \
    asm volatile("st.async.shared::cluster.mbarrier::complete_tx::bytes.v4.b32 [%0], {%1,%2,%3,%4}, [%5];" \
                 :: "r"(addr), "r"(__float_as_uint((v).x)), "r"(__float_as_uint((v).y)), \
                    "r"(__float_as_uint((v).z)), "r"(__float_as_uint((v).w)), "r"(mbar) : "memory")

__device__ __forceinline__ void mbar_wait(uint32_t addr, uint32_t phase) {
    uint32_t done;
    asm volatile(
        "{\n\t.reg .pred p;\n\t"
        "mbarrier.try_wait.parity.acquire.cluster.shared::cta.b64 p, [%1], %2;\n\t"
        "selp.b32 %0, 1, 0, p;\n\t}"
        : "=r"(done) : "r"(addr), "r"(phase) : "memory");
    while (!done) {
        asm volatile(
            "{\n\t.reg .pred p;\n\t"
            "mbarrier.try_wait.parity.acquire.cluster.shared::cta.b64 p, [%1], %2, 0x989680;\n\t"
            "selp.b32 %0, 1, 0, p;\n\t}"
            : "=r"(done) : "r"(addr), "r"(phase) : "memory");
    }
}

// Packed fp32x2 FMA (Blackwell)
#define FFMA2(acc, a, b) \
    asm("fma.rn.f32x2 %0, %1, %2, %0;" : "+l"(acc) : "l"(a), "l"(b))

__device__ __forceinline__ float2 unpack2(unsigned long long v) {
    float2 f;
    asm("mov.b64 {%0, %1}, %2;" : "=f"(f.x), "=f"(f.y) : "l"(v));
    return f;
}

// MUFU-based activations (ex2/rcp approx: rel err ~2^-22)
__device__ __forceinline__ float fast_sigmoid(float x) {
    float e, r;
    asm("ex2.approx.f32 %0, %1;" : "=f"(e) : "f"(x * -1.442695040888963f));
    asm("rcp.approx.f32 %0, %1;" : "=f"(r) : "f"(1.f + e));
    return r;
}
__device__ __forceinline__ float fast_tanh(float x) {
    float e, r;
    asm("ex2.approx.f32 %0, %1;" : "=f"(e) : "f"(x * -2.885390081777927f));
    asm("rcp.approx.f32 %0, %1;" : "=f"(r) : "f"(1.f + e));
    return fmaf(2.f, r, -1.f);
}

// ---------------------------------------------------------------------------
// Kernel 2: GRU recurrence. 16 clusters x 8 CTAs. Owner-partitioned weights:
// CTA c holds w_hh rows {gate*256 + c*32 + j : gate in 0..2, j in 0..31} in
// registers as f32x2 k-pairs, so its matvec output is exactly the hg values
// its own gating threads consume -> NO cross-CTA hg scatter.
// Per step:  matvec -> STS partials -> __syncthreads -> (128 gating threads)
//   reduce + gate + stage h_new (512B, dest layout) -> bar.sync(128) ->
//   256 x st.async.v4 (32 msgs x 8 dests) -> all threads mbar_wait(h).
// h double-buffered with 2 ping-pong tx barriers (sender skew <= 1 phase).
// ---------------------------------------------------------------------------
__global__ __launch_bounds__(768, 1) void gru_scan(
    const float* __restrict__ Whh,   // [G_, H_]
    const float* __restrict__ bn_g)  // [H_]
{
    __shared__ __align__(16) float hPf[2][1024];   // interleaved h, 2 buffers
    __shared__ __align__(16) float part[8 * 4 * 96]; // [kc][bm][row]
    __shared__ __align__(16) float4 stage[32];     // h_new in dest float order
    __shared__ __align__(8) unsigned long long h_mbar[2];

    const int tid   = threadIdx.x;
    const uint32_t crank = ctarank();
    const int bbase = (blockIdx.x >> 3) * 4;

    const int warp = tid >> 5, lane = tid & 31;
    const int kc = warp / 3;                 // k-chunk 0..7 (32 k each)
    const int r  = (warp % 3) * 32 + lane;   // local row 0..95 (gate = r>>5)

    // Owner-partitioned weight rows: gate*256 + crank*32 + (r&31)
    unsigned long long w2[16];
    {
        const int grow = (r >> 5) * 256 + (int)crank * 32 + (r & 31);
        const ulonglong2* wr = reinterpret_cast<const ulonglong2*>(
            Whh + (size_t)grow * H_ + kc * 32);
#pragma unroll
        for (int i = 0; i < 8; i++) { ulonglong2 v = wr[i]; w2[2*i] = v.x; w2[2*i+1] = v.y; }
    }

    const uint32_t hP_base  = smem_u32(hPf);
    const uint32_t hm_base  = smem_u32(h_mbar);

    // Gating thread (tid<128): owns h index jg = crank*32 + gj for batch gbm.
    const int gbm = tid >> 5, gj = tid & 31;
    // float index inside a 1024-float h buffer (interleaved layout)
    const int sidx = (gj >> 1) * 8 + (gbm >> 1) * 4 + (gbm & 1) * 2 + (gj & 1);
    const int hflt = (int)crank * 128 + sidx;
    float bnv = 0.f;
    if (tid < 128) bnv = bn_g[(int)crank * 32 + gj];

    // Send setup: thread (tid<128) sends stage[msg] to dests d0=tid>>5, d1=d0+4.
    uint32_t send_a0 = 0, send_a1 = 0, send_m0 = 0, send_m1 = 0;
    if (tid < 128) {
        const int msg = tid & 31;
        const uint32_t d0 = (uint32_t)(tid >> 5), d1 = d0 + 4;
        uint32_t dst = hP_base + (uint32_t)crank * 512 + (uint32_t)msg * 16;
        send_a0 = mapa_u32(dst, d0);
        send_a1 = mapa_u32(dst, d1);
        send_m0 = mapa_u32(hm_base, d0);
        send_m1 = mapa_u32(hm_base, d1);
    }

    if (tid == 0) {
        MBAR_INIT(hm_base, 1);
        MBAR_INIT(hm_base + 8, 1);
    }
    for (int i = tid; i < 2048; i += 768) ((float*)hPf)[i] = 0.f;
    __syncthreads();
    CLUSTER_SYNC();   // mbarriers + zeroed h visible cluster-wide

    for (int t = 0; t < T_; t++) {
        const int buf = t & 1;
        if (tid == 0) MBAR_EXPECT_TX(hm_base + 8 * buf, 4096);

        // Prefetch igates (covered by matvec)
        float ig_r = 0.f, ig_z = 0.f, ig_n = 0.f;
        if (tid < 128) {
            size_t base = ((size_t)t * B_ + (bbase + gbm)) * G_ + (int)crank * 32 + gj;
            ig_r = g_igates[base];
            ig_z = g_igates[base + 256];
            ig_n = g_igates[base + 512];
        }

        // Matvec: 16 k-pairs, packed f32x2 FMAs, uniform LDS.128 broadcasts
        unsigned long long a0 = 0ull, a1 = 0ull, a2 = 0ull, a3 = 0ull;
        {
            const ulonglong2* hv = reinterpret_cast<const ulonglong2*>(&hPf[buf][kc * 128]);
#pragma unroll
            for (int kp = 0; kp < 16; kp++) {
                ulonglong2 U0 = hv[2 * kp];      // bm0,bm1 k-pairs
                ulonglong2 U1 = hv[2 * kp + 1];  // bm2,bm3 k-pairs
                FFMA2(a0, w2[kp], U0.x);
                FFMA2(a1, w2[kp], U0.y);
                FFMA2(a2, w2[kp], U1.x);
                FFMA2(a3, w2[kp], U1.y);
            }
        }
        {
            float2 f0 = unpack2(a0), f1 = unpack2(a1), f2 = unpack2(a2), f3 = unpack2(a3);
            // part[kc][bm][r] — conflict-free STS (bank = r&31 = lane)
            part[kc * 384 +   0 + r] = f0.x + f0.y;
            part[kc * 384 +  96 + r] = f1.x + f1.y;
            part[kc * 384 + 192 + r] = f2.x + f2.y;
            part[kc * 384 + 288 + r] = f3.x + f3.y;
        }
        __syncthreads();

        if (tid < 128) {
            // Reduce the 8 k-chunks for rows gj (r), 32+gj (z), 64+gj (n)
            float hr = 0.f, hz = 0.f, hn = 0.f;
            const float* pb = part + gbm * 96 + gj;
#pragma unroll
            for (int q = 0; q < 8; q++) {
                hr += pb[q * 384];
                hz += pb[q * 384 + 32];
                hn += pb[q * 384 + 64];
            }
            float rr = fast_sigmoid(ig_r + hr);
            float zz = fast_sigmoid(ig_z + hz);
            float nn = fast_tanh(ig_n + rr * (hn + bnv));
            float hold = hPf[buf][hflt];
            float hnew = nn + zz * (hold - nn);
            ((float*)stage)[sidx] = hnew;

            asm volatile("bar.sync 1, 128;" ::: "memory");

            // Broadcast: 32 x 16B messages to each of 8 CTAs (2 per thread)
            float4 v = stage[tid & 31];
            uint32_t off = (uint32_t)(buf ^ 1) * 4096;
            ST_ASYNC_V4(send_a0 + off, v, send_m0 + 8u * buf);
            ST_ASYNC_V4(send_a1 + off, v, send_m1 + 8u * buf);
        }

        // Everyone: wait for the full next-h (4096 B from 8 CTAs)
        mbar_wait(hm_base + 8 * buf, (uint32_t)((t >> 1) & 1));
    }

    // Final h is in buffer 0 (T even). Rank 0 writes its cluster's 4 batches.
    if (crank == 0) {
        const float* hf = hPf[0];
        for (int idx = tid; idx < 4 * H_; idx += 768) {
            int bm = idx >> 8, k = idx & 255;
            int fo = (k >> 1) * 8 + (bm >> 1) * 4 + (bm & 1) * 2 + (k & 1);
            g_hfinal[(bbase + bm) * H_ + k] = hf[fo];
        }
    }
    CLUSTER_SYNC();
}

// ---------------------------------------------------------------------------
// Kernel 3: out = h_final @ w_proj^T + b_proj
// ---------------------------------------------------------------------------
__global__ __launch_bounds__(128) void proj_kernel(
    const float* __restrict__ Wp,
    const float* __restrict__ bp,
    float* __restrict__ out)
{
    __shared__ float hs[H_];
    int b = blockIdx.x;
    for (int k = threadIdx.x; k < H_; k += 128) hs[k] = g_hfinal[b * H_ + k];
    __syncthreads();
    int c = threadIdx.x;
    float acc = bp[c];
    const float* wr = Wp + (size_t)c * H_;
#pragma unroll 8
    for (int k = 0; k < H_; k++) acc = fmaf(hs[k], wr[k], acc);
    out[b * C_ + c] = acc;
}

// ---------------------------------------------------------------------------
// Launch
// ---------------------------------------------------------------------------
extern "C" void kernel_launch(void* const* d_in, const int* in_sizes, int n_in,
                              void* d_out, int out_size)
{
    const float* x      = (const float*)d_in[0];
    const float* w_ih   = (const float*)d_in[1];
    const float* w_hh   = (const float*)d_in[2];
    const float* b      = (const float*)d_in[3];
    const float* bn     = (const float*)d_in[4];
    const float* w_proj = (const float*)d_in[5];
    const float* b_proj = (const float*)d_in[6];
    float* out = (float*)d_out;

    dim3 g1((B_ * T_) / 128, G_ / 128);
    igates_gemm<<<g1, 256>>>(x, w_ih, b);

    {
        cudaLaunchConfig_t cfg = {};
        cfg.gridDim  = dim3(128, 1, 1);
        cfg.blockDim = dim3(768, 1, 1);
        cfg.dynamicSmemBytes = 0;
        cfg.stream = 0;
        cudaLaunchAttribute attr[1];
        attr[0].id = cudaLaunchAttributeClusterDimension;
        attr[0].val.clusterDim.x = 8;
        attr[0].val.clusterDim.y = 1;
        attr[0].val.clusterDim.z = 1;
        cfg.attrs = attr;
        cfg.numAttrs = 1;
        cudaLaunchKernelEx(&cfg, gru_scan, w_hh, bn);
    }

    proj_kernel<<<B_, 128>>>(w_proj, b_proj, out);
}

// round 6
// speedup vs baseline: 2.1554x; 1.2856x over previous
#include <cuda_runtime.h>
#include <cstdint>
#include <math.h>

// Problem constants
#define B_   64
#define T_   4096
#define D_   128
#define H_   256
#define G_   768   // 3*H
#define C_   128

__device__ float g_igates[(size_t)T_ * B_ * G_];
__device__ float g_hfinal[B_ * H_];

// ---------------------------------------------------------------------------
// Kernel 1: igates = x @ w_ih^T + b   (fp32 SIMT sgemm, 128x128x16 tiles)
// ---------------------------------------------------------------------------
__global__ __launch_bounds__(256) void igates_gemm(
    const float* __restrict__ X,
    const float* __restrict__ W,
    const float* __restrict__ bias)
{
    __shared__ float As[16][128];
    __shared__ float Bs[16][128];

    const int tid = threadIdx.x;
    const int mb  = blockIdx.x * 128;
    const int nb  = blockIdx.y * 128;
    const int tx  = tid & 15;
    const int ty  = tid >> 4;
    const int lq  = tid & 3;
    const int lm  = tid >> 2;

    float acc[8][8];
#pragma unroll
    for (int i = 0; i < 8; i++)
#pragma unroll
        for (int j = 0; j < 8; j++) acc[i][j] = 0.f;

    const float* Xp0 = X + (size_t)(mb + lm) * D_ + 4 * lq;
    const float* Xp1 = Xp0 + (size_t)64 * D_;
    const float* Wp0 = W + (size_t)(nb + lm) * D_ + 4 * lq;
    const float* Wp1 = Wp0 + (size_t)64 * D_;

#pragma unroll
    for (int kt = 0; kt < D_; kt += 16) {
        float4 a0 = *(const float4*)(Xp0 + kt);
        float4 a1 = *(const float4*)(Xp1 + kt);
        float4 b0 = *(const float4*)(Wp0 + kt);
        float4 b1 = *(const float4*)(Wp1 + kt);
        __syncthreads();
        As[4*lq+0][lm]    = a0.x; As[4*lq+1][lm]    = a0.y; As[4*lq+2][lm]    = a0.z; As[4*lq+3][lm]    = a0.w;
        As[4*lq+0][lm+64] = a1.x; As[4*lq+1][lm+64] = a1.y; As[4*lq+2][lm+64] = a1.z; As[4*lq+3][lm+64] = a1.w;
        Bs[4*lq+0][lm]    = b0.x; Bs[4*lq+1][lm]    = b0.y; Bs[4*lq+2][lm]    = b0.z; Bs[4*lq+3][lm]    = b0.w;
        Bs[4*lq+0][lm+64] = b1.x; Bs[4*lq+1][lm+64] = b1.y; Bs[4*lq+2][lm+64] = b1.z; Bs[4*lq+3][lm+64] = b1.w;
        __syncthreads();
#pragma unroll
        for (int k = 0; k < 16; k++) {
            float a[8], bb[8];
            *(float4*)&a[0]  = *(const float4*)&As[k][ty * 8];
            *(float4*)&a[4]  = *(const float4*)&As[k][ty * 8 + 4];
            *(float4*)&bb[0] = *(const float4*)&Bs[k][tx * 8];
            *(float4*)&bb[4] = *(const float4*)&Bs[k][tx * 8 + 4];
#pragma unroll
            for (int i = 0; i < 8; i++)
#pragma unroll
                for (int j = 0; j < 8; j++)
                    acc[i][j] = fmaf(a[i], bb[j], acc[i][j]);
        }
    }

    float bv[8];
#pragma unroll
    for (int j = 0; j < 8; j++) bv[j] = bias[nb + tx * 8 + j];

#pragma unroll
    for (int i = 0; i < 8; i++) {
        int m    = mb + ty * 8 + i;
        int bidx = m >> 12;
        int tt   = m & (T_ - 1);
        float* op = g_igates + ((size_t)tt * B_ + bidx) * G_ + nb + tx * 8;
        float4 v0 = make_float4(acc[i][0] + bv[0], acc[i][1] + bv[1],
                                acc[i][2] + bv[2], acc[i][3] + bv[3]);
        float4 v1 = make_float4(acc[i][4] + bv[4], acc[i][5] + bv[5],
                                acc[i][6] + bv[6], acc[i][7] + bv[7]);
        *(float4*)op       = v0;
        *(float4*)(op + 4) = v1;
    }
}

// ---------------------------------------------------------------------------
// Cluster / DSMEM / mbarrier helpers
// ---------------------------------------------------------------------------
__device__ __forceinline__ uint32_t smem_u32(const void* p) {
    uint32_t a;
    asm("{ .reg .u64 t; cvta.to.shared.u64 t, %1; cvt.u32.u64 %0, t; }"
        : "=r"(a) : "l"(p));
    return a;
}
__device__ __forceinline__ uint32_t mapa_u32(uint32_t a, uint32_t rank) {
    uint32_t r;
    asm("mapa.shared::cluster.u32 %0, %1, %2;" : "=r"(r) : "r"(a), "r"(rank));
    return r;
}
__device__ __forceinline__ uint32_t ctarank() {
    uint32_t r;
    asm("mov.u32 %0, %%cluster_ctarank;" : "=r"(r));
    return r;
}
#define CLUSTER_SYNC() do { \
    asm volatile("barrier.cluster.arrive.aligned;" ::: "memory"); \
    asm volatile("barrier.cluster.wait.aligned;"   ::: "memory"); \
} while (0)

#define MBAR_INIT(a, c) \
    asm volatile("mbarrier.init.shared.b64 [%0], %1;" :: "r"(a), "r"(c) : "memory")
#define MBAR_EXPECT_TX(a, tx) \
    asm volatile("mbarrier.arrive.expect_tx.shared.b64 _, [%0], %1;" :: "r"(a), "r"(tx) : "memory")

// Bulk DSMEM copy: local SMEM -> remote CTA SMEM, tx-signals remote mbarrier.
#define BULK_S2S(dst, src, bytes, mbar) \
    asm volatile("cp.async.bulk.shared::cluster.shared::cta.mbarrier::complete_tx::bytes [%0], [%1], %2, [%3];" \
                 :: "r"(dst), "r"(src), "r"(bytes), "r"(mbar) : "memory")

#define FENCE_ASYNC_SHARED() \
    asm volatile("fence.proxy.async.shared::cta;" ::: "memory")

__device__ __forceinline__ void mbar_wait(uint32_t addr, uint32_t phase) {
    uint32_t done;
    asm volatile(
        "{\n\t.reg .pred p;\n\t"
        "mbarrier.try_wait.parity.acquire.cluster.shared::cta.b64 p, [%1], %2;\n\t"
        "selp.b32 %0, 1, 0, p;\n\t}"
        : "=r"(done) : "r"(addr), "r"(phase) : "memory");
    while (!done) {
        asm volatile(
            "{\n\t.reg .pred p;\n\t"
            "mbarrier.try_wait.parity.acquire.cluster.shared::cta.b64 p, [%1], %2, 0x989680;\n\t"
            "selp.b32 %0, 1, 0, p;\n\t}"
            : "=r"(done) : "r"(addr), "r"(phase) : "memory");
    }
}

// Packed fp32x2 FMA (Blackwell)
#define FFMA2(acc, a, b) \
    asm("fma.rn.f32x2 %0, %1, %2, %0;" : "+l"(acc) : "l"(a), "l"(b))

__device__ __forceinline__ float2 unpack2(unsigned long long v) {
    float2 f;
    asm("mov.b64 {%0, %1}, %2;" : "=f"(f.x), "=f"(f.y) : "l"(v));
    return f;
}

// MUFU-based activations (ex2/rcp approx: rel err ~2^-22)
__device__ __forceinline__ float fast_sigmoid(float x) {
    float e, r;
    asm("ex2.approx.f32 %0, %1;" : "=f"(e) : "f"(x * -1.442695040888963f));
    asm("rcp.approx.f32 %0, %1;" : "=f"(r) : "f"(1.f + e));
    return r;
}
__device__ __forceinline__ float fast_tanh(float x) {
    float e, r;
    asm("ex2.approx.f32 %0, %1;" : "=f"(e) : "f"(x * -2.885390081777927f));
    asm("rcp.approx.f32 %0, %1;" : "=f"(r) : "f"(1.f + e));
    return fmaf(2.f, r, -1.f);
}

// ---------------------------------------------------------------------------
// Kernel 2: GRU recurrence. 16 clusters x 8 CTAs, owner-partitioned weights.
// Per-source pipelining: h buffer block [src*128 .. src*128+128) is fed by ONE
// 512B cp.async.bulk from CTA src, signalling mbar[buf][src]. Matvec warp kc
// waits ONLY mbar[buf][kc] -> starts as soon as that source lands.
// Producer warps (4..23) use bar.arrive (never block on gating); gating warps
// (0..3) bar.sync, reduce double-buffered partials, gate (h in registers),
// stage 512B, and 8 threads issue the 8 bulk copies.
// ---------------------------------------------------------------------------
__global__ __launch_bounds__(768, 1) void gru_scan(
    const float* __restrict__ Whh,   // [G_, H_]
    const float* __restrict__ bn_g)  // [H_]
{
    __shared__ __align__(16) float hPf[2][1024];      // interleaved h, per-source blocks
    __shared__ __align__(16) float part[2][8 * 4 * 96]; // double-buffered partials
    __shared__ __align__(16) float stage[2][128];     // outgoing h_new (dest layout)
    __shared__ __align__(8) unsigned long long mbars[16]; // [buf][src]

    const int tid   = threadIdx.x;
    const uint32_t crank = ctarank();
    const int bbase = (blockIdx.x >> 3) * 4;

    const int warp = tid >> 5, lane = tid & 31;
    const int kc = warp / 3;                 // k-chunk / source 0..7
    const int r  = (warp % 3) * 32 + lane;   // local row 0..95 (gate = r>>5)

    // Owner-partitioned weight rows: gate*256 + crank*32 + (r&31), as f32x2 pairs
    unsigned long long w2[16];
    {
        const int grow = (r >> 5) * 256 + (int)crank * 32 + (r & 31);
        const ulonglong2* wr = reinterpret_cast<const ulonglong2*>(
            Whh + (size_t)grow * H_ + kc * 32);
#pragma unroll
        for (int i = 0; i < 8; i++) { ulonglong2 v = wr[i]; w2[2*i] = v.x; w2[2*i+1] = v.y; }
    }

    const uint32_t hP_base    = smem_u32(hPf);
    const uint32_t stage_base = smem_u32(stage);
    const uint32_t mbar_base  = smem_u32(mbars);
    const uint32_t my_wait    = mbar_base + (uint32_t)kc * 8;  // + buf*64 per step

    // Gating thread (tid<128): owns h index crank*32+gj for batch gbm; h in reg.
    const int gbm = tid >> 5, gj = tid & 31;
    const int sidx = (gj >> 1) * 8 + (gbm >> 1) * 4 + (gbm & 1) * 2 + (gj & 1);
    float bnv = 0.f, hreg = 0.f;
    const float* igp = g_igates + (size_t)(bbase + gbm) * G_ + (int)crank * 32 + gj;
    if (tid < 128) bnv = bn_g[(int)crank * 32 + gj];

    // Send setup (tid<8): this CTA's 512B block goes to dest CTA = tid.
    uint32_t send_dst = 0, send_mb = 0;
    if (tid < 8) {
        send_dst = mapa_u32(hP_base + (uint32_t)crank * 512, (uint32_t)tid);
        send_mb  = mapa_u32(mbar_base + (uint32_t)crank * 8, (uint32_t)tid);
    }

    // Init: barriers (count=1 arrival, tx-driven), zero h buffer 0.
    if (tid < 16) MBAR_INIT(mbar_base + tid * 8, 1);
    __syncthreads();
    if (tid < 8) MBAR_EXPECT_TX(mbar_base + 64 + tid * 8, 512);  // prime buf1 (t=1)
    for (int i = tid; i < 1024; i += 768) hPf[0][i] = 0.f;
    __syncthreads();
    CLUSTER_SYNC();   // barriers + zeros visible before any sends

    for (int t = 0; t < T_; t++) {
        const int buf = t & 1;
        // phase: buf1 uses (t>>1)&1; buf0 skipped its first use (t=0) -> +1
        const uint32_t phase = (uint32_t)(((t >> 1) + (buf ^ 1)) & 1);

        // igates prefetch (independent of h)
        float ig_r = 0.f, ig_z = 0.f, ig_n = 0.f;
        if (tid < 128) {
            const float* p = igp + (size_t)t * (B_ * G_);
            ig_r = p[0]; ig_z = p[256]; ig_n = p[512];
        }

        // Wait only for this warp's source block
        if (t > 0) mbar_wait(my_wait + (uint32_t)buf * 64, phase);

        // Matvec: 16 k-pairs, packed f32x2 FMAs, uniform LDS.128 broadcasts
        unsigned long long a0 = 0ull, a1 = 0ull, a2 = 0ull, a3 = 0ull;
        {
            const ulonglong2* hv = reinterpret_cast<const ulonglong2*>(&hPf[buf][kc * 128]);
#pragma unroll
            for (int kp = 0; kp < 16; kp++) {
                ulonglong2 U0 = hv[2 * kp];      // bm0,bm1 k-pairs
                ulonglong2 U1 = hv[2 * kp + 1];  // bm2,bm3 k-pairs
                FFMA2(a0, w2[kp], U0.x);
                FFMA2(a1, w2[kp], U0.y);
                FFMA2(a2, w2[kp], U1.x);
                FFMA2(a3, w2[kp], U1.y);
            }
        }
        {
            float2 f0 = unpack2(a0), f1 = unpack2(a1), f2 = unpack2(a2), f3 = unpack2(a3);
            float* pb = part[buf] + kc * 384;
            pb[      r] = f0.x + f0.y;
            pb[ 96 + r] = f1.x + f1.y;
            pb[192 + r] = f2.x + f2.y;
            pb[288 + r] = f3.x + f3.y;
        }

        if (warp >= 4) {
            // Producer: signal partials done, loop straight to next wait.
            asm volatile("bar.arrive 2, 768;" ::: "memory");
            continue;
        }

        // Gating warps (0..3 == tid<128): wait for all partials
        asm volatile("bar.sync 2, 768;" ::: "memory");

        // All per-source waits for this buf have completed (every warp passed
        // its wait before bar 2) -> safe to re-arm expects for step t+2.
        if (tid < 8) MBAR_EXPECT_TX(mbar_base + (uint32_t)buf * 64 + (uint32_t)tid * 8, 512);

        // Reduce 8 k-chunks for rows gj / 32+gj / 64+gj of batch gbm
        float hr = 0.f, hz = 0.f, hn = 0.f;
        {
            const float* pb = part[buf] + gbm * 96 + gj;
#pragma unroll
            for (int q = 0; q < 8; q++) {
                hr += pb[q * 384];
                hz += pb[q * 384 + 32];
                hn += pb[q * 384 + 64];
            }
        }
        float rr = fast_sigmoid(ig_r + hr);
        float zz = fast_sigmoid(ig_z + hz);
        float nn = fast_tanh(ig_n + rr * (hn + bnv));
        hreg = nn + zz * (hreg - nn);

        if (t == T_ - 1) {
            g_hfinal[(bbase + gbm) * H_ + (int)crank * 32 + gj] = hreg;
        } else {
            stage[buf][sidx] = hreg;
            FENCE_ASYNC_SHARED();
            asm volatile("bar.sync 1, 128;" ::: "memory");
            if (tid < 8) {
                const uint32_t nb = (uint32_t)(buf ^ 1);
                BULK_S2S(send_dst + nb * 4096,
                         stage_base + (uint32_t)buf * 512,
                         512,
                         send_mb + nb * 64);
            }
        }
    }

    CLUSTER_SYNC();  // no CTA exits while peers' inbound copies may reference it
}

// ---------------------------------------------------------------------------
// Kernel 3: out = h_final @ w_proj^T + b_proj
// ---------------------------------------------------------------------------
__global__ __launch_bounds__(128) void proj_kernel(
    const float* __restrict__ Wp,
    const float* __restrict__ bp,
    float* __restrict__ out)
{
    __shared__ float hs[H_];
    int b = blockIdx.x;
    for (int k = threadIdx.x; k < H_; k += 128) hs[k] = g_hfinal[b * H_ + k];
    __syncthreads();
    int c = threadIdx.x;
    float acc = bp[c];
    const float* wr = Wp + (size_t)c * H_;
#pragma unroll 8
    for (int k = 0; k < H_; k++) acc = fmaf(hs[k], wr[k], acc);
    out[b * C_ + c] = acc;
}

// ---------------------------------------------------------------------------
// Launch
// ---------------------------------------------------------------------------
extern "C" void kernel_launch(void* const* d_in, const int* in_sizes, int n_in,
                              void* d_out, int out_size)
{
    const float* x      = (const float*)d_in[0];
    const float* w_ih   = (const float*)d_in[1];
    const float* w_hh   = (const float*)d_in[2];
    const float* b      = (const float*)d_in[3];
    const float* bn     = (const float*)d_in[4];
    const float* w_proj = (const float*)d_in[5];
    const float* b_proj = (const float*)d_in[6];
    float* out = (float*)d_out;

    dim3 g1((B_ * T_) / 128, G_ / 128);
    igates_gemm<<<g1, 256>>>(x, w_ih, b);

    {
        cudaLaunchConfig_t cfg = {};
        cfg.gridDim  = dim3(128, 1, 1);
        cfg.blockDim = dim3(768, 1, 1);
        cfg.dynamicSmemBytes = 0;
        cfg.stream = 0;
        cudaLaunchAttribute attr[1];
        attr[0].id = cudaLaunchAttributeClusterDimension;
        attr[0].val.clusterDim.x = 8;
        attr[0].val.clusterDim.y = 1;
        attr[0].val.clusterDim.z = 1;
        cfg.attrs = attr;
        cfg.numAttrs = 1;
        cudaLaunchKernelEx(&cfg, gru_scan, w_hh, bn);
    }

    proj_kernel<<<B_, 128>>>(w_proj, b_proj, out);
}

// round 7
// speedup vs baseline: 2.2326x; 1.0358x over previous
#include <cuda_runtime.h>
#include <cstdint>
#include <math.h>

// Problem constants
#define B_   64
#define T_   4096
#define D_   128
#define H_   256
#define G_   768   // 3*H
#define C_   128

__device__ float g_igates[(size_t)T_ * B_ * G_];
__device__ float g_hfinal[B_ * H_];

// Packed fp32x2 FMA (Blackwell)
#define FFMA2(acc, a, b) \
    asm("fma.rn.f32x2 %0, %1, %2, %0;" : "+l"(acc) : "l"(a), "l"(b))
#define PACK2(out, lo, hi) \
    asm("mov.b64 %0, {%1, %2};" : "=l"(out) : "f"(lo), "f"(hi))

__device__ __forceinline__ float2 unpack2(unsigned long long v) {
    float2 f;
    asm("mov.b64 {%0, %1}, %2;" : "=f"(f.x), "=f"(f.y) : "l"(v));
    return f;
}

// ---------------------------------------------------------------------------
// Kernel 1: igates = x @ w_ih^T + b   (f32x2 sgemm, 128x128x16 tiles)
// ---------------------------------------------------------------------------
__global__ __launch_bounds__(256) void igates_gemm(
    const float* __restrict__ X,
    const float* __restrict__ W,
    const float* __restrict__ bias)
{
    __shared__ float As[16][128];
    __shared__ float Bs[16][128];

    const int tid = threadIdx.x;
    const int mb  = blockIdx.x * 128;
    const int nb  = blockIdx.y * 128;
    const int tx  = tid & 15;
    const int ty  = tid >> 4;
    const int lq  = tid & 3;
    const int lm  = tid >> 2;

    unsigned long long acc2[8][4];
#pragma unroll
    for (int i = 0; i < 8; i++)
#pragma unroll
        for (int j = 0; j < 4; j++) acc2[i][j] = 0ull;

    const float* Xp0 = X + (size_t)(mb + lm) * D_ + 4 * lq;
    const float* Xp1 = Xp0 + (size_t)64 * D_;
    const float* Wp0 = W + (size_t)(nb + lm) * D_ + 4 * lq;
    const float* Wp1 = Wp0 + (size_t)64 * D_;

#pragma unroll
    for (int kt = 0; kt < D_; kt += 16) {
        float4 a0 = *(const float4*)(Xp0 + kt);
        float4 a1 = *(const float4*)(Xp1 + kt);
        float4 b0 = *(const float4*)(Wp0 + kt);
        float4 b1 = *(const float4*)(Wp1 + kt);
        __syncthreads();
        As[4*lq+0][lm]    = a0.x; As[4*lq+1][lm]    = a0.y; As[4*lq+2][lm]    = a0.z; As[4*lq+3][lm]    = a0.w;
        As[4*lq+0][lm+64] = a1.x; As[4*lq+1][lm+64] = a1.y; As[4*lq+2][lm+64] = a1.z; As[4*lq+3][lm+64] = a1.w;
        Bs[4*lq+0][lm]    = b0.x; Bs[4*lq+1][lm]    = b0.y; Bs[4*lq+2][lm]    = b0.z; Bs[4*lq+3][lm]    = b0.w;
        Bs[4*lq+0][lm+64] = b1.x; Bs[4*lq+1][lm+64] = b1.y; Bs[4*lq+2][lm+64] = b1.z; Bs[4*lq+3][lm+64] = b1.w;
        __syncthreads();
#pragma unroll
        for (int k = 0; k < 16; k++) {
            float a[8];
            unsigned long long bb2[4];
            *(float4*)&a[0] = *(const float4*)&As[k][ty * 8];
            *(float4*)&a[4] = *(const float4*)&As[k][ty * 8 + 4];
            {
                ulonglong2 q0 = *(const ulonglong2*)&Bs[k][tx * 8];
                ulonglong2 q1 = *(const ulonglong2*)&Bs[k][tx * 8 + 4];
                bb2[0] = q0.x; bb2[1] = q0.y; bb2[2] = q1.x; bb2[3] = q1.y;
            }
#pragma unroll
            for (int i = 0; i < 8; i++) {
                unsigned long long ai;
                PACK2(ai, a[i], a[i]);
                FFMA2(acc2[i][0], ai, bb2[0]);
                FFMA2(acc2[i][1], ai, bb2[1]);
                FFMA2(acc2[i][2], ai, bb2[2]);
                FFMA2(acc2[i][3], ai, bb2[3]);
            }
        }
    }

    float bv[8];
#pragma unroll
    for (int j = 0; j < 8; j++) bv[j] = bias[nb + tx * 8 + j];

#pragma unroll
    for (int i = 0; i < 8; i++) {
        int m    = mb + ty * 8 + i;
        int bidx = m >> 12;
        int tt   = m & (T_ - 1);
        float* op = g_igates + ((size_t)tt * B_ + bidx) * G_ + nb + tx * 8;
        float2 p0 = unpack2(acc2[i][0]), p1 = unpack2(acc2[i][1]);
        float2 p2 = unpack2(acc2[i][2]), p3 = unpack2(acc2[i][3]);
        float4 v0 = make_float4(p0.x + bv[0], p0.y + bv[1], p1.x + bv[2], p1.y + bv[3]);
        float4 v1 = make_float4(p2.x + bv[4], p2.y + bv[5], p3.x + bv[6], p3.y + bv[7]);
        *(float4*)op       = v0;
        *(float4*)(op + 4) = v1;
    }
}

// ---------------------------------------------------------------------------
// Cluster / DSMEM / mbarrier helpers
// ---------------------------------------------------------------------------
__device__ __forceinline__ uint32_t smem_u32(const void* p) {
    uint32_t a;
    asm("{ .reg .u64 t; cvta.to.shared.u64 t, %1; cvt.u32.u64 %0, t; }"
        : "=r"(a) : "l"(p));
    return a;
}
__device__ __forceinline__ uint32_t mapa_u32(uint32_t a, uint32_t rank) {
    uint32_t r;
    asm("mapa.shared::cluster.u32 %0, %1, %2;" : "=r"(r) : "r"(a), "r"(rank));
    return r;
}
__device__ __forceinline__ uint32_t ctarank() {
    uint32_t r;
    asm("mov.u32 %0, %%cluster_ctarank;" : "=r"(r));
    return r;
}
#define CLUSTER_SYNC() do { \
    asm volatile("barrier.cluster.arrive.aligned;" ::: "memory"); \
    asm volatile("barrier.cluster.wait.aligned;"   ::: "memory"); \
} while (0)

#define MBAR_INIT(a, c) \
    asm volatile("mbarrier.init.shared.b64 [%0], %1;" :: "r"(a), "r"(c) : "memory")
#define MBAR_EXPECT_TX(a, tx) \
    asm volatile("mbarrier.arrive.expect_tx.shared.b64 _, [%0], %1;" :: "r"(a), "r"(tx) : "memory")

// Remote 16B store with mbarrier tx completion.
#define ST_ASYNC_V4(addr, x, y, z, w, mbar) \
    asm volatile("st.async.shared::cluster.mbarrier::complete_tx::bytes.v4.b32 [%0], {%1,%2,%3,%4}, [%5];" \
                 :: "r"(addr), "r"(__float_as_uint(x)), "r"(__float_as_uint(y)), \
                    "r"(__float_as_uint(z)), "r"(__float_as_uint(w)), "r"(mbar) : "memory")

// cta-scope acquire: canonical for async-proxy data delivered into LOCAL smem.
__device__ __forceinline__ void mbar_wait(uint32_t addr, uint32_t phase) {
    uint32_t done;
    asm volatile(
        "{\n\t.reg .pred p;\n\t"
        "mbarrier.try_wait.parity.acquire.cta.shared::cta.b64 p, [%1], %2;\n\t"
        "selp.b32 %0, 1, 0, p;\n\t}"
        : "=r"(done) : "r"(addr), "r"(phase) : "memory");
    while (!done) {
        asm volatile(
            "{\n\t.reg .pred p;\n\t"
            "mbarrier.try_wait.parity.acquire.cta.shared::cta.b64 p, [%1], %2, 0x989680;\n\t"
            "selp.b32 %0, 1, 0, p;\n\t}"
            : "=r"(done) : "r"(addr), "r"(phase) : "memory");
    }
}

// MUFU-based activations (ex2/rcp approx: rel err ~2^-22)
__device__ __forceinline__ float fast_sigmoid(float x) {
    float e, r;
    asm("ex2.approx.f32 %0, %1;" : "=f"(e) : "f"(x * -1.442695040888963f));
    asm("rcp.approx.f32 %0, %1;" : "=f"(r) : "f"(1.f + e));
    return r;
}
__device__ __forceinline__ float fast_tanh(float x) {
    float e, r;
    asm("ex2.approx.f32 %0, %1;" : "=f"(e) : "f"(x * -2.885390081777927f));
    asm("rcp.approx.f32 %0, %1;" : "=f"(r) : "f"(1.f + e));
    return fmaf(2.f, r, -1.f);
}

// ---------------------------------------------------------------------------
// Kernel 2: GRU recurrence. 16 clusters x 8 CTAs, owner-partitioned weights.
// Per-source h blocks are bm-major: hPf[buf][src*128 + bm*32 + j]. Block src
// is fed by 32 st.async.v4 from src's 4 gating warps (each owns a contiguous
// 128B), signalling per-source barrier mbar[buf][src] (512B tx). Matvec warp
// kc waits ONLY its source. Gating: reduce partials, gate in registers,
// shuffle-pack quads, 2x st.async.v4 per lane -> no staging/fence/named-bar.
// ---------------------------------------------------------------------------
__global__ __launch_bounds__(768, 1) void gru_scan(
    const float* __restrict__ Whh,   // [G_, H_]
    const float* __restrict__ bn_g)  // [H_]
{
    __shared__ __align__(16) float hPf[2][1024];        // per-source bm-major blocks
    __shared__ __align__(16) float part[2][8 * 4 * 96]; // double-buffered partials
    __shared__ __align__(8) unsigned long long mbars[16]; // [buf][src]

    const int tid   = threadIdx.x;
    const uint32_t crank = ctarank();
    const int bbase = (blockIdx.x >> 3) * 4;

    const int warp = tid >> 5, lane = tid & 31;
    const int kc = warp / 3;                 // k-chunk / source 0..7
    const int r  = (warp % 3) * 32 + lane;   // local row 0..95 (gate = r>>5)

    // Owner-partitioned weight rows: gate*256 + crank*32 + (r&31), f32x2 pairs
    unsigned long long w2[16];
    {
        const int grow = (r >> 5) * 256 + (int)crank * 32 + (r & 31);
        const ulonglong2* wr = reinterpret_cast<const ulonglong2*>(
            Whh + (size_t)grow * H_ + kc * 32);
#pragma unroll
        for (int i = 0; i < 8; i++) { ulonglong2 v = wr[i]; w2[2*i] = v.x; w2[2*i+1] = v.y; }
    }

    const uint32_t hP_base   = smem_u32(hPf);
    const uint32_t mbar_base = smem_u32(mbars);
    const uint32_t my_wait   = mbar_base + (uint32_t)kc * 8;  // + buf*64 per step

    // Gating thread (tid<128): h index crank*32+gj, batch gbm; h in register.
    const int gbm = tid >> 5, gj = tid & 31;
    float bnv = 0.f, hreg = 0.f;
    const float* igp = g_igates + (size_t)(bbase + gbm) * G_ + (int)crank * 32 + gj;
    if (tid < 128) bnv = bn_g[(int)crank * 32 + gj];

    // Send setup (gating lanes): lane gj handles quad c = gj>>2 to dests
    // d0 = gj&3 and d1 = d0+4. Dest float4 = hPf[buf'][crank*128+gbm*32+4c..].
    uint32_t send_a0 = 0, send_a1 = 0, send_m0 = 0, send_m1 = 0;
    if (tid < 128) {
        const uint32_t c  = (uint32_t)(gj >> 2);
        const uint32_t d0 = (uint32_t)(gj & 3), d1 = d0 + 4;
        uint32_t base = hP_base + (uint32_t)crank * 512 + (uint32_t)gbm * 128 + c * 16;
        send_a0 = mapa_u32(base, d0);
        send_a1 = mapa_u32(base, d1);
        send_m0 = mapa_u32(mbar_base + (uint32_t)crank * 8, d0);
        send_m1 = mapa_u32(mbar_base + (uint32_t)crank * 8, d1);
    }

    // Init barriers (1 arrival + tx), zero h buffer 0, prime buf1 expects.
    if (tid < 16) MBAR_INIT(mbar_base + tid * 8, 1);
    __syncthreads();
    if (tid < 8) MBAR_EXPECT_TX(mbar_base + 64 + tid * 8, 512);
    for (int i = tid; i < 1024; i += 768) hPf[0][i] = 0.f;
    __syncthreads();
    CLUSTER_SYNC();   // barriers + zeros visible before any sends

    for (int t = 0; t < T_; t++) {
        const int buf = t & 1;
        const uint32_t phase = (uint32_t)(((t >> 1) + (buf ^ 1)) & 1);

        // igates prefetch (independent of h; covered by wait+matvec)
        float ig_r = 0.f, ig_z = 0.f, ig_n = 0.f;
        if (tid < 128) {
            const float* p = igp + (size_t)t * (B_ * G_);
            ig_r = p[0]; ig_z = p[256]; ig_n = p[512];
        }

        // Wait only for this warp's source block
        if (t > 0) mbar_wait(my_wait + (uint32_t)buf * 64, phase);

        // Matvec: per c-iter 4x LDS.128 (one per batch) + 8 FFMA2
        unsigned long long a0 = 0ull, a1 = 0ull, a2 = 0ull, a3 = 0ull;
        {
            const ulonglong2* hv = reinterpret_cast<const ulonglong2*>(&hPf[buf][kc * 128]);
#pragma unroll
            for (int c = 0; c < 8; c++) {
                ulonglong2 u0 = hv[c];
                ulonglong2 u1 = hv[8 + c];
                ulonglong2 u2 = hv[16 + c];
                ulonglong2 u3 = hv[24 + c];
                FFMA2(a0, w2[2*c], u0.x); FFMA2(a0, w2[2*c+1], u0.y);
                FFMA2(a1, w2[2*c], u1.x); FFMA2(a1, w2[2*c+1], u1.y);
                FFMA2(a2, w2[2*c], u2.x); FFMA2(a2, w2[2*c+1], u2.y);
                FFMA2(a3, w2[2*c], u3.x); FFMA2(a3, w2[2*c+1], u3.y);
            }
        }
        {
            float2 f0 = unpack2(a0), f1 = unpack2(a1), f2 = unpack2(a2), f3 = unpack2(a3);
            float* pb = part[buf] + kc * 384;
            pb[      r] = f0.x + f0.y;
            pb[ 96 + r] = f1.x + f1.y;
            pb[192 + r] = f2.x + f2.y;
            pb[288 + r] = f3.x + f3.y;
        }

        if (warp >= 4) {
            asm volatile("bar.arrive 2, 768;" ::: "memory");
            continue;
        }

        // Gating warps: wait all partials
        asm volatile("bar.sync 2, 768;" ::: "memory");

        // All waits for barriers[buf] completed -> re-arm for step t+2.
        if (tid < 8) MBAR_EXPECT_TX(mbar_base + (uint32_t)buf * 64 + (uint32_t)tid * 8, 512);

        // Reduce 8 k-chunks for rows gj / 32+gj / 64+gj of batch gbm
        float hr = 0.f, hz = 0.f, hn = 0.f;
        {
            const float* pb = part[buf] + gbm * 96 + gj;
#pragma unroll
            for (int q = 0; q < 8; q++) {
                hr += pb[q * 384];
                hz += pb[q * 384 + 32];
                hn += pb[q * 384 + 64];
            }
        }
        float rr = fast_sigmoid(ig_r + hr);
        float zz = fast_sigmoid(ig_z + hz);
        float nn = fast_tanh(ig_n + rr * (hn + bnv));
        hreg = nn + zz * (hreg - nn);

        if (t == T_ - 1) {
            g_hfinal[(bbase + gbm) * H_ + (int)crank * 32 + gj] = hreg;
        } else {
            // Shuffle-pack quad (gj&~3 .. +3) and send straight from registers.
            const int qb = gj & ~3;
            float v0 = __shfl_sync(0xffffffffu, hreg, qb + 0);
            float v1 = __shfl_sync(0xffffffffu, hreg, qb + 1);
            float v2 = __shfl_sync(0xffffffffu, hreg, qb + 2);
            float v3 = __shfl_sync(0xffffffffu, hreg, qb + 3);
            const uint32_t off = (uint32_t)(buf ^ 1) * 4096;
            const uint32_t mof = (uint32_t)(buf ^ 1) * 64;
            ST_ASYNC_V4(send_a0 + off, v0, v1, v2, v3, send_m0 + mof);
            ST_ASYNC_V4(send_a1 + off, v0, v1, v2, v3, send_m1 + mof);
        }
    }

    CLUSTER_SYNC();  // no CTA exits while peers' inbound stores may reference it
}

// ---------------------------------------------------------------------------
// Kernel 3: out = h_final @ w_proj^T + b_proj
// ---------------------------------------------------------------------------
__global__ __launch_bounds__(128) void proj_kernel(
    const float* __restrict__ Wp,
    const float* __restrict__ bp,
    float* __restrict__ out)
{
    __shared__ float hs[H_];
    int b = blockIdx.x;
    for (int k = threadIdx.x; k < H_; k += 128) hs[k] = g_hfinal[b * H_ + k];
    __syncthreads();
    int c = threadIdx.x;
    float acc = bp[c];
    const float* wr = Wp + (size_t)c * H_;
#pragma unroll 8
    for (int k = 0; k < H_; k++) acc = fmaf(hs[k], wr[k], acc);
    out[b * C_ + c] = acc;
}

// ---------------------------------------------------------------------------
// Launch
// ---------------------------------------------------------------------------
extern "C" void kernel_launch(void* const* d_in, const int* in_sizes, int n_in,
                              void* d_out, int out_size)
{
    const float* x      = (const float*)d_in[0];
    const float* w_ih   = (const float*)d_in[1];
    const float* w_hh   = (const float*)d_in[2];
    const float* b      = (const float*)d_in[3];
    const float* bn     = (const float*)d_in[4];
    const float* w_proj = (const float*)d_in[5];
    const float* b_proj = (const float*)d_in[6];
    float* out = (float*)d_out;

    dim3 g1((B_ * T_) / 128, G_ / 128);
    igates_gemm<<<g1, 256>>>(x, w_ih, b);

    {
        cudaLaunchConfig_t cfg = {};
        cfg.gridDim  = dim3(128, 1, 1);
        cfg.blockDim = dim3(768, 1, 1);
        cfg.dynamicSmemBytes = 0;
        cfg.stream = 0;
        cudaLaunchAttribute attr[1];
        attr[0].id = cudaLaunchAttributeClusterDimension;
        attr[0].val.clusterDim.x = 8;
        attr[0].val.clusterDim.y = 1;
        attr[0].val.clusterDim.z = 1;
        cfg.attrs = attr;
        cfg.numAttrs = 1;
        cudaLaunchKernelEx(&cfg, gru_scan, w_hh, bn);
    }

    proj_kernel<<<B_, 128>>>(w_proj, b_proj, out);
}